// round 1
// baseline (speedup 1.0000x reference)
#include <cuda_runtime.h>
#include <cstdint>

// ---------------- problem constants ----------------
#define CL 32
#define NL 128
#define CV 8
#define NV 64
#define PSZ (128*128*32)          // one transposed plane, floats
#define VSZ (64*64*64*8)          // transposed volume, floats

// smem layout (floats)
#define SM_LINES   0          // 3*32*128 = 12288
#define SM_WT      12288      // 3*1024 (Wx^T, Wy^T, Wz^T), [j*32+c]
#define SM_W1T     15360      // 128*40, [k*40+j]
#define SM_B       20480      // bx(32) by(32) bz(32)
#define SM_B1      20576      // 128
#define SM_W2      20704      // 128
#define SM_FLOATS  20832
#define SMEM_BYTES (SM_FLOATS*4)

// device scratch (channel-last layouts)
__device__ __align__(128) float g_plane_t[3*PSZ];  // [p][(row*128+col)*32 + c]
__device__ __align__(128) float g_vol_t[VSZ];      // [((z*64+y)*64+x)*8 + c]

typedef unsigned long long ull;

__device__ __forceinline__ ull pk2(float a, float b){ ull r; asm("mov.b64 %0,{%1,%2};":"=l"(r):"f"(a),"f"(b)); return r; }
__device__ __forceinline__ void upk2(ull v, float& a, float& b){ asm("mov.b64 {%0,%1}, %2;":"=f"(a),"=f"(b):"l"(v)); }
__device__ __forceinline__ ull ffma2(ull a, ull b, ull c){ ull d; asm("fma.rn.f32x2 %0,%1,%2,%3;":"=l"(d):"l"(a),"l"(b),"l"(c)); return d; }
__device__ __forceinline__ ull fadd2(ull a, ull b){ ull d; asm("add.rn.f32x2 %0,%1,%2;":"=l"(d):"l"(a),"l"(b)); return d; }
__device__ __forceinline__ ull fmul2(ull a, ull b){ ull d; asm("mul.rn.f32x2 %0,%1,%2;":"=l"(d):"l"(a),"l"(b)); return d; }
__device__ __forceinline__ ull relu2(ull v){ float a,b; upk2(v,a,b); return pk2(fmaxf(a,0.f), fmaxf(b,0.f)); }
__device__ __forceinline__ float hsum2(ull v){ float a,b; upk2(v,a,b); return a+b; }

// ---------------- preprocessing: transpose to channel-last ----------------
__global__ void k_transpose(const float* __restrict__ pxy, const float* __restrict__ pyz,
                            const float* __restrict__ pxz, const float* __restrict__ vol)
{
    int i = blockIdx.x * blockDim.x + threadIdx.x;
    if (i < 3*PSZ) {
        int p  = i / PSZ;
        int r  = i - p*PSZ;
        int hw = r >> 5;       // (row*128 + col)
        int c  = r & 31;
        const float* s = (p == 0) ? pxy : (p == 1) ? pyz : pxz;
        g_plane_t[i] = s[c*16384 + hw];
    }
    int j = i - 3*PSZ;
    if (j >= 0 && j < VSZ) {
        int vox = j >> 3;
        int c   = j & 7;
        g_vol_t[j] = vol[c*262144 + vox];
    }
}

// ---------------- per-point sampling helpers ----------------
// line: smem layout (C,N) original. eL[i] = (relu(e[2i]), relu(e[2i+1]))
__device__ __forceinline__ void line_sample(const float* __restrict__ L, int i, float w, ull* eL)
{
#pragma unroll
    for (int c = 0; c < 16; c++) {
        float a0 = L[(2*c  )*128 + i];
        float b0 = L[(2*c  )*128 + i + 1];
        float a1 = L[(2*c+1)*128 + i];
        float b1 = L[(2*c+1)*128 + i + 1];
        float e0 = fmaxf(fmaf(w, b0 - a0, a0), 0.f);
        float e1 = fmaxf(fmaf(w, b1 - a1, a1), 0.f);
        eL[c] = pk2(e0, e1);
    }
}

// plane: channel-last global, bilinear, relu'd, packed
__device__ __forceinline__ void plane_sample(const float* __restrict__ pl, int col, int row,
                                             float wc, float wr, ull* eP)
{
    const float* base = pl + (((row*128 + col)) << 5);
    const ulonglong2* t00 = (const ulonglong2*)(base);
    const ulonglong2* t01 = (const ulonglong2*)(base + 32);      // col+1
    const ulonglong2* t10 = (const ulonglong2*)(base + 4096);    // row+1
    const ulonglong2* t11 = (const ulonglong2*)(base + 4128);
    float iwc = 1.f - wc, iwr = 1.f - wr;
    ull W00 = pk2(iwc*iwr, iwc*iwr);
    ull W01 = pk2( wc*iwr,  wc*iwr);
    ull W10 = pk2(iwc* wr, iwc* wr);
    ull W11 = pk2( wc* wr,  wc* wr);
#pragma unroll
    for (int q = 0; q < 8; q++) {
        ulonglong2 A = t00[q], B = t01[q], C = t10[q], D = t11[q];
        ull r0 = fmul2(W00, A.x); r0 = ffma2(W01, B.x, r0); r0 = ffma2(W10, C.x, r0); r0 = ffma2(W11, D.x, r0);
        ull r1 = fmul2(W00, A.y); r1 = ffma2(W01, B.y, r1); r1 = ffma2(W10, C.y, r1); r1 = ffma2(W11, D.y, r1);
        eP[2*q]   = relu2(r0);
        eP[2*q+1] = relu2(r1);
    }
}

// feat[j] (+)= (b[j] + eL.Wt_j) * (b[j] + eP.Wt_j)
template<bool ADD>
__device__ __forceinline__ void axis_combine(const ull* eL, const ull* eP,
                                             const float* __restrict__ Wt,
                                             const float* __restrict__ bias,
                                             float* feat)
{
#pragma unroll 4
    for (int j = 0; j < 32; j++) {
        const ulonglong2* w = (const ulonglong2*)(Wt + (j << 5));
        ull a0 = 0ull, a1 = 0ull, p0 = 0ull, p1 = 0ull;
#pragma unroll
        for (int q = 0; q < 8; q++) {
            ulonglong2 ww = w[q];
            a0 = ffma2(eL[2*q],   ww.x, a0);
            a1 = ffma2(eL[2*q+1], ww.y, a1);
            p0 = ffma2(eP[2*q],   ww.x, p0);
            p1 = ffma2(eP[2*q+1], ww.y, p1);
        }
        float b  = bias[j];
        float t1 = b + hsum2(fadd2(a0, a1));
        float t2 = b + hsum2(fadd2(p0, p1));
        if (ADD) feat[j] += t1 * t2; else feat[j] = t1 * t2;
    }
}

// ---------------- main fused kernel ----------------
__global__ void __launch_bounds__(256, 2) k_main(
    const float* __restrict__ coords,
    const float* __restrict__ lx, const float* __restrict__ ly, const float* __restrict__ lz,
    const float* __restrict__ Wx, const float* __restrict__ bx,
    const float* __restrict__ Wy, const float* __restrict__ by,
    const float* __restrict__ Wz, const float* __restrict__ bz,
    const float* __restrict__ W1, const float* __restrict__ b1,
    const float* __restrict__ W2, const float* __restrict__ b2,
    float* __restrict__ out, int M)
{
    extern __shared__ float sm[];

    // cooperative fill: lines (as-is, (C,N)), Wx/Wy/Wz transposed, W1 transposed, biases
    for (int i = threadIdx.x; i < 4096; i += 256) {
        sm[SM_LINES          + i] = lx[i];
        sm[SM_LINES +  4096  + i] = ly[i];
        sm[SM_LINES +  8192  + i] = lz[i];
    }
    for (int i = threadIdx.x; i < 1024; i += 256) {
        int j = i & 31, c = i >> 5;                 // input W[c*32+j]
        sm[SM_WT        + j*32 + c] = Wx[i];
        sm[SM_WT + 1024 + j*32 + c] = Wy[i];
        sm[SM_WT + 2048 + j*32 + c] = Wz[i];
    }
    for (int i = threadIdx.x; i < 5120; i += 256) {
        int j = i >> 7, k = i & 127;                // input W1[j*128+k]
        sm[SM_W1T + k*40 + j] = W1[i];
    }
    if (threadIdx.x < 32) {
        sm[SM_B      + threadIdx.x] = bx[threadIdx.x];
        sm[SM_B + 32 + threadIdx.x] = by[threadIdx.x];
        sm[SM_B + 64 + threadIdx.x] = bz[threadIdx.x];
    }
    for (int i = threadIdx.x; i < 128; i += 256) {
        sm[SM_B1 + i] = b1[i];
        sm[SM_W2 + i] = W2[i];
    }
    __syncthreads();

    int m = blockIdx.x * blockDim.x + threadIdx.x;
    if (m >= M) return;

    float x = coords[3*m + 0];
    float y = coords[3*m + 1];
    float z = coords[3*m + 2];

    // 128-grid indices (lines & planes share it)
    float fx = (x + 1.f) * (0.5f * 127.f);
    float fy = (y + 1.f) * (0.5f * 127.f);
    float fz = (z + 1.f) * (0.5f * 127.f);
    float fix = fminf(fmaxf(floorf(fx), 0.f), 126.f);
    float fiy = fminf(fmaxf(floorf(fy), 0.f), 126.f);
    float fiz = fminf(fmaxf(floorf(fz), 0.f), 126.f);
    int ix = (int)fix, iy = (int)fiy, iz = (int)fiz;
    float wxp = fx - fix, wyp = fy - fiy, wzp = fz - fiz;

    // 64-grid (volume)
    float gx = (x + 1.f) * (0.5f * 63.f);
    float gy = (y + 1.f) * (0.5f * 63.f);
    float gz = (z + 1.f) * (0.5f * 63.f);
    float gvx = fminf(fmaxf(floorf(gx), 0.f), 62.f);
    float gvy = fminf(fmaxf(floorf(gy), 0.f), 62.f);
    float gvz = fminf(fmaxf(floorf(gz), 0.f), 62.f);
    int vx = (int)gvx, vy = (int)gvy, vz = (int)gvz;
    float ux = gx - gvx, uy = gy - gvy, uz = gz - gvz;

    float feat[32];
    ull eL[16], eP[16];

    // ---- axis X: xtran(line_x, Wx) * yztran(plane_yz, Wx)
    line_sample(sm + SM_LINES, ix, wxp, eL);
    plane_sample(g_plane_t + PSZ, iy, iz, wyp, wzp, eP);       // plane_yz: col=y, row=z
    axis_combine<false>(eL, eP, sm + SM_WT,        sm + SM_B,      feat);

    // ---- axis Y: ytran(line_y, Wy) * xztran(plane_xz, Wy)
    line_sample(sm + SM_LINES + 4096, iy, wyp, eL);
    plane_sample(g_plane_t + 2*PSZ, ix, iz, wxp, wzp, eP);     // plane_xz: col=x, row=z
    axis_combine<true>(eL, eP, sm + SM_WT + 1024,  sm + SM_B + 32, feat);

    // ---- axis Z: ztran(line_z, Wz) * xytran(plane_xy, Wz)
    line_sample(sm + SM_LINES + 8192, iz, wzp, eL);
    plane_sample(g_plane_t, ix, iy, wxp, wyp, eP);             // plane_xy: col=x, row=y
    axis_combine<true>(eL, eP, sm + SM_WT + 2048,  sm + SM_B + 64, feat);

    // ---- volume trilinear (raw, no relu), packed v2[4] = 8 channels
    ull v2[4] = {0ull, 0ull, 0ull, 0ull};
    {
        const float* vb = g_vol_t + ((((vz*64 + vy)*64) + vx) << 3);
        float iux = 1.f - ux, iuy = 1.f - uy, iuz = 1.f - uz;
#pragma unroll
        for (int corner = 0; corner < 8; corner++) {
            int dx = corner & 1, dy = (corner >> 1) & 1, dz = corner >> 2;
            float wgt = (dx ? ux : iux) * (dy ? uy : iuy) * (dz ? uz : iuz);
            ull Wc = pk2(wgt, wgt);
            const ulonglong2* t = (const ulonglong2*)(vb + dx*8 + dy*512 + dz*32768);
            ulonglong2 A = t[0], B = t[1];
            v2[0] = ffma2(Wc, A.x, v2[0]);
            v2[1] = ffma2(Wc, A.y, v2[1]);
            v2[2] = ffma2(Wc, B.x, v2[2]);
            v2[3] = ffma2(Wc, B.y, v2[3]);
        }
    }

    // ---- final MLP: h = relu([feat, xyz] @ W1 + b1); out = h @ W2 + b2
    ull f2[16];
#pragma unroll
    for (int q = 0; q < 16; q++) f2[q] = pk2(feat[2*q], feat[2*q+1]);

    float acc = b2[0];
#pragma unroll 2
    for (int k = 0; k < 128; k++) {
        const ulonglong2* w = (const ulonglong2*)(sm + SM_W1T + k*40);
        ull a0 = 0ull, a1 = 0ull;
#pragma unroll
        for (int q = 0; q < 8; q++) {
            ulonglong2 ww = w[q];
            a0 = ffma2(f2[2*q],   ww.x, a0);
            a1 = ffma2(f2[2*q+1], ww.y, a1);
        }
        ulonglong2 w8 = w[8], w9 = w[9];
        a0 = ffma2(v2[0], w8.x, a0);
        a1 = ffma2(v2[1], w8.y, a1);
        a0 = ffma2(v2[2], w9.x, a0);
        a1 = ffma2(v2[3], w9.y, a1);
        float h = sm[SM_B1 + k] + hsum2(fadd2(a0, a1));
        acc = fmaf(fmaxf(h, 0.f), sm[SM_W2 + k], acc);
    }
    out[m] = acc;
}

// ---------------- launch ----------------
extern "C" void kernel_launch(void* const* d_in, const int* in_sizes, int n_in,
                              void* d_out, int out_size)
{
    const float* coords = (const float*)d_in[0];
    const float* lx  = (const float*)d_in[1];
    const float* ly  = (const float*)d_in[2];
    const float* lz  = (const float*)d_in[3];
    const float* pxy = (const float*)d_in[4];
    const float* pyz = (const float*)d_in[5];
    const float* pxz = (const float*)d_in[6];
    const float* vol = (const float*)d_in[7];
    const float* Wx  = (const float*)d_in[8];
    const float* bx  = (const float*)d_in[9];
    const float* Wy  = (const float*)d_in[10];
    const float* by  = (const float*)d_in[11];
    const float* Wz  = (const float*)d_in[12];
    const float* bz  = (const float*)d_in[13];
    const float* W1  = (const float*)d_in[14];
    const float* b1  = (const float*)d_in[15];
    const float* W2  = (const float*)d_in[16];
    const float* b2  = (const float*)d_in[17];
    float* out = (float*)d_out;

    int M = in_sizes[0] / 3;

    cudaFuncSetAttribute(k_main, cudaFuncAttributeMaxDynamicSharedMemorySize, SMEM_BYTES);

    const int TPOSE_ELEMS = 3*PSZ + VSZ;            // 3670016
    k_transpose<<<(TPOSE_ELEMS + 255) / 256, 256>>>(pxy, pyz, pxz, vol);

    k_main<<<(M + 255) / 256, 256, SMEM_BYTES>>>(coords, lx, ly, lz,
                                                 Wx, bx, Wy, by, Wz, bz,
                                                 W1, b1, W2, b2, out, M);
}

// round 2
// speedup vs baseline: 1.0149x; 1.0149x over previous
#include <cuda_runtime.h>
#include <cuda_fp16.h>
#include <cstdint>

// ---------------- problem constants ----------------
#define PSZ (128*128*32)          // one plane, elements
#define VSZ (64*64*64*8)          // volume, elements

// smem layout (floats)
#define SM_LINES   0          // 3 axes * 128 rows * 36 floats (row = 32ch + 4 pad)
#define SM_WT      13824      // 3*1024 (Wx^T, Wy^T, Wz^T), [j*32+c]
#define SM_W1T     16896      // 128*40, [k*40+j]
#define SM_B       22016      // bx(32) by(32) bz(32)
#define SM_B1      22112      // 128
#define SM_W2      22240      // 128
#define SM_FLOATS  22368
#define SMEM_BYTES (SM_FLOATS*4)

#define LROW 36               // line row stride in floats

// device scratch: channel-last fp16 grids
__device__ __align__(128) __half g_plane_h[3*PSZ];  // [p][(row*128+col)*32 + c]
__device__ __align__(128) __half g_vol_h[VSZ];      // [((z*64+y)*64+x)*8 + c]

typedef unsigned long long ull;

__device__ __forceinline__ ull pk2(float a, float b){ ull r; asm("mov.b64 %0,{%1,%2};":"=l"(r):"f"(a),"f"(b)); return r; }
__device__ __forceinline__ void upk2(ull v, float& a, float& b){ asm("mov.b64 {%0,%1}, %2;":"=f"(a),"=f"(b):"l"(v)); }
__device__ __forceinline__ ull ffma2(ull a, ull b, ull c){ ull d; asm("fma.rn.f32x2 %0,%1,%2,%3;":"=l"(d):"l"(a),"l"(b),"l"(c)); return d; }
__device__ __forceinline__ ull fadd2(ull a, ull b){ ull d; asm("add.rn.f32x2 %0,%1,%2;":"=l"(d):"l"(a),"l"(b)); return d; }
__device__ __forceinline__ float hsum2(ull v){ float a,b; upk2(v,a,b); return a+b; }

// ---------------- preprocessing: transpose to channel-last fp16 ----------------
// planes: src (32, 16384) -> dst (16384, 32) fp16.  32x32 smem tile.
__global__ void k_tplane(const float* __restrict__ pxy, const float* __restrict__ pyz,
                         const float* __restrict__ pxz)
{
    __shared__ float tile[32][33];
    int p   = blockIdx.y;                    // which plane
    int hw0 = blockIdx.x * 32;
    const float* src = (p == 0) ? pxy : (p == 1) ? pyz : pxz;
    __half* dst = g_plane_h + p * PSZ;

    int tx = threadIdx.x;         // 0..31
    int ty = threadIdx.y;         // 0..7
    // read: coalesced in hw
    #pragma unroll
    for (int cc = ty; cc < 32; cc += 8)
        tile[cc][tx] = src[cc * 16384 + hw0 + tx];
    __syncthreads();
    // write: coalesced in (hw*32 + c)
    #pragma unroll
    for (int hwL = ty; hwL < 32; hwL += 8)
        dst[(hw0 + hwL) * 32 + tx] = __float2half(tile[tx][hwL]);
}

// volume: src (8, 262144) -> dst (262144, 8) fp16
__global__ void k_tvol(const float* __restrict__ vol)
{
    __shared__ float t[8][129];
    int vox0 = blockIdx.x * 128;
    int tid  = threadIdx.x;       // 0..255
    int w    = tid >> 5;          // warp = channel
    int lane = tid & 31;
    #pragma unroll
    for (int j = lane; j < 128; j += 32)
        t[w][j] = vol[w * 262144 + vox0 + j];
    __syncthreads();
    #pragma unroll
    for (int rep = 0; rep < 4; rep++) {
        int idx = rep * 256 + tid;            // 0..1023
        int v   = idx >> 3, c = idx & 7;
        g_vol_h[vox0 * 8 + idx] = __float2half(t[c][v]);
    }
}

// ---------------- per-point sampling helpers ----------------
// line: smem channel-last rows, fp32.  eL[q] = relu(lerp) packed f32x2
__device__ __forceinline__ void line_sample(const float* __restrict__ row0, float w, ull* eL)
{
    const float4* A4 = (const float4*)row0;
    const float4* B4 = (const float4*)(row0 + LROW);
#pragma unroll
    for (int q = 0; q < 8; q++) {
        float4 a = A4[q], b = B4[q];
        float e0 = fmaxf(fmaf(w, b.x - a.x, a.x), 0.f);
        float e1 = fmaxf(fmaf(w, b.y - a.y, a.y), 0.f);
        float e2 = fmaxf(fmaf(w, b.z - a.z, a.z), 0.f);
        float e3 = fmaxf(fmaf(w, b.w - a.w, a.w), 0.f);
        eL[2*q]   = pk2(e0, e1);
        eL[2*q+1] = pk2(e2, e3);
    }
}

// plane: channel-last fp16 global, bilinear in half2, relu'd, packed f32x2
__device__ __forceinline__ void plane_sample(const __half* __restrict__ pl, int col, int row,
                                             float wc, float wr, ull* eP)
{
    const uint4* t00 = (const uint4*)(pl + (row*128 + col)*32);
    const uint4* t01 = t00 + 4;      // col+1: +32 halves = 4 uint4
    const uint4* t10 = t00 + 512;    // row+1: +4096 halves
    const uint4* t11 = t10 + 4;
    float iwc = 1.f - wc, iwr = 1.f - wr;
    __half2 w00 = __float2half2_rn(iwc*iwr);
    __half2 w01 = __float2half2_rn( wc*iwr);
    __half2 w10 = __float2half2_rn(iwc* wr);
    __half2 w11 = __float2half2_rn( wc* wr);
#pragma unroll
    for (int h = 0; h < 4; h++) {
        uint4 A = t00[h], B = t01[h], C = t10[h], D = t11[h];
        const __half2* a = (const __half2*)&A;
        const __half2* b = (const __half2*)&B;
        const __half2* c = (const __half2*)&C;
        const __half2* d = (const __half2*)&D;
#pragma unroll
        for (int k = 0; k < 4; k++) {
            __half2 acc = __hmul2(w00, a[k]);
            __half2 ac2 = __hmul2(w01, b[k]);
            acc = __hfma2(w10, c[k], acc);
            ac2 = __hfma2(w11, d[k], ac2);
            acc = __hadd2(acc, ac2);
            float2 f = __half22float2(acc);
            eP[h*4 + k] = pk2(fmaxf(f.x, 0.f), fmaxf(f.y, 0.f));
        }
    }
}

// feat[j] (+)= (b[j] + eL.Wt_j) * (b[j] + eP.Wt_j)
template<bool ADD>
__device__ __forceinline__ void axis_combine(const ull* eL, const ull* eP,
                                             const float* __restrict__ Wt,
                                             const float* __restrict__ bias,
                                             float* feat)
{
#pragma unroll 4
    for (int j = 0; j < 32; j++) {
        const ulonglong2* w = (const ulonglong2*)(Wt + (j << 5));
        ull a0 = 0ull, a1 = 0ull, p0 = 0ull, p1 = 0ull;
#pragma unroll
        for (int q = 0; q < 8; q++) {
            ulonglong2 ww = w[q];
            a0 = ffma2(eL[2*q],   ww.x, a0);
            a1 = ffma2(eL[2*q+1], ww.y, a1);
            p0 = ffma2(eP[2*q],   ww.x, p0);
            p1 = ffma2(eP[2*q+1], ww.y, p1);
        }
        float b  = bias[j];
        float t1 = b + hsum2(fadd2(a0, a1));
        float t2 = b + hsum2(fadd2(p0, p1));
        if (ADD) feat[j] += t1 * t2; else feat[j] = t1 * t2;
    }
}

// ---------------- main fused kernel ----------------
__global__ void __launch_bounds__(256, 2) k_main(
    const float* __restrict__ coords,
    const float* __restrict__ lx, const float* __restrict__ ly, const float* __restrict__ lz,
    const float* __restrict__ Wx, const float* __restrict__ bx,
    const float* __restrict__ Wy, const float* __restrict__ by,
    const float* __restrict__ Wz, const float* __restrict__ bz,
    const float* __restrict__ W1, const float* __restrict__ b1,
    const float* __restrict__ W2, const float* __restrict__ b2,
    float* __restrict__ out, int M)
{
    extern __shared__ float sm[];

    // lines: channel-last rows, stride LROW
    for (int i = threadIdx.x; i < 4096; i += 256) {
        int pos = i >> 5, c = i & 31;
        sm[SM_LINES             + pos*LROW + c] = lx[c*128 + pos];
        sm[SM_LINES + 128*LROW  + pos*LROW + c] = ly[c*128 + pos];
        sm[SM_LINES + 256*LROW  + pos*LROW + c] = lz[c*128 + pos];
    }
    for (int i = threadIdx.x; i < 1024; i += 256) {
        int j = i & 31, c = i >> 5;                 // input W[c*32+j]
        sm[SM_WT        + j*32 + c] = Wx[i];
        sm[SM_WT + 1024 + j*32 + c] = Wy[i];
        sm[SM_WT + 2048 + j*32 + c] = Wz[i];
    }
    for (int i = threadIdx.x; i < 5120; i += 256) {
        int j = i >> 7, k = i & 127;                // input W1[j*128+k]
        sm[SM_W1T + k*40 + j] = W1[i];
    }
    if (threadIdx.x < 32) {
        sm[SM_B      + threadIdx.x] = bx[threadIdx.x];
        sm[SM_B + 32 + threadIdx.x] = by[threadIdx.x];
        sm[SM_B + 64 + threadIdx.x] = bz[threadIdx.x];
    }
    for (int i = threadIdx.x; i < 128; i += 256) {
        sm[SM_B1 + i] = b1[i];
        sm[SM_W2 + i] = W2[i];
    }
    __syncthreads();

    int m = blockIdx.x * blockDim.x + threadIdx.x;
    if (m >= M) return;

    float x = coords[3*m + 0];
    float y = coords[3*m + 1];
    float z = coords[3*m + 2];

    // 128-grid indices (lines & planes)
    float fx = (x + 1.f) * (0.5f * 127.f);
    float fy = (y + 1.f) * (0.5f * 127.f);
    float fz = (z + 1.f) * (0.5f * 127.f);
    float fix = fminf(fmaxf(floorf(fx), 0.f), 126.f);
    float fiy = fminf(fmaxf(floorf(fy), 0.f), 126.f);
    float fiz = fminf(fmaxf(floorf(fz), 0.f), 126.f);
    int ix = (int)fix, iy = (int)fiy, iz = (int)fiz;
    float wxp = fx - fix, wyp = fy - fiy, wzp = fz - fiz;

    // 64-grid (volume)
    float gx = (x + 1.f) * (0.5f * 63.f);
    float gy = (y + 1.f) * (0.5f * 63.f);
    float gz = (z + 1.f) * (0.5f * 63.f);
    float gvx = fminf(fmaxf(floorf(gx), 0.f), 62.f);
    float gvy = fminf(fmaxf(floorf(gy), 0.f), 62.f);
    float gvz = fminf(fmaxf(floorf(gz), 0.f), 62.f);
    int vx = (int)gvx, vy = (int)gvy, vz = (int)gvz;
    float ux = gx - gvx, uy = gy - gvy, uz = gz - gvz;

    float feat[32];
    ull eL[16], eP[16];

    // ---- axis X: xtran(line_x, Wx) * yztran(plane_yz, Wx)
    line_sample(sm + SM_LINES + ix*LROW, wxp, eL);
    plane_sample(g_plane_h + PSZ, iy, iz, wyp, wzp, eP);       // plane_yz: col=y, row=z
    axis_combine<false>(eL, eP, sm + SM_WT,        sm + SM_B,      feat);

    // ---- axis Y: ytran(line_y, Wy) * xztran(plane_xz, Wy)
    line_sample(sm + SM_LINES + 128*LROW + iy*LROW, wyp, eL);
    plane_sample(g_plane_h + 2*PSZ, ix, iz, wxp, wzp, eP);     // plane_xz: col=x, row=z
    axis_combine<true>(eL, eP, sm + SM_WT + 1024,  sm + SM_B + 32, feat);

    // ---- axis Z: ztran(line_z, Wz) * xytran(plane_xy, Wz)
    line_sample(sm + SM_LINES + 256*LROW + iz*LROW, wzp, eL);
    plane_sample(g_plane_h, ix, iy, wxp, wyp, eP);             // plane_xy: col=x, row=y
    axis_combine<true>(eL, eP, sm + SM_WT + 2048,  sm + SM_B + 64, feat);

    // ---- volume trilinear (raw, no relu) in half2, -> v2[4] f32x2 (8 channels)
    ull v2[4];
    {
        const uint4* vb = (const uint4*)(g_vol_h + ((((vz*64 + vy)*64) + vx) << 3));
        float iux = 1.f - ux, iuy = 1.f - uy, iuz = 1.f - uz;
        __half2 va[4] = {__half2(), __half2(), __half2(), __half2()};
        va[0] = __float2half2_rn(0.f); va[1] = va[0]; va[2] = va[0]; va[3] = va[0];
#pragma unroll
        for (int corner = 0; corner < 8; corner++) {
            int dx = corner & 1, dy = (corner >> 1) & 1, dz = corner >> 2;
            float wgt = (dx ? ux : iux) * (dy ? uy : iuy) * (dz ? uz : iuz);
            __half2 w2 = __float2half2_rn(wgt);
            uint4 T = vb[dx + dy*64 + dz*4096];
            const __half2* t = (const __half2*)&T;
            va[0] = __hfma2(w2, t[0], va[0]);
            va[1] = __hfma2(w2, t[1], va[1]);
            va[2] = __hfma2(w2, t[2], va[2]);
            va[3] = __hfma2(w2, t[3], va[3]);
        }
#pragma unroll
        for (int q = 0; q < 4; q++) {
            float2 f = __half22float2(va[q]);
            v2[q] = pk2(f.x, f.y);
        }
    }

    // ---- final MLP: h = relu([feat, xyz_e] @ W1 + b1); out = h @ W2 + b2
    ull f2[16];
#pragma unroll
    for (int q = 0; q < 16; q++) f2[q] = pk2(feat[2*q], feat[2*q+1]);

    float acc = b2[0];
#pragma unroll 2
    for (int k = 0; k < 128; k++) {
        const ulonglong2* w = (const ulonglong2*)(sm + SM_W1T + k*40);
        ull a0 = 0ull, a1 = 0ull;
#pragma unroll
        for (int q = 0; q < 8; q++) {
            ulonglong2 ww = w[q];
            a0 = ffma2(f2[2*q],   ww.x, a0);
            a1 = ffma2(f2[2*q+1], ww.y, a1);
        }
        ulonglong2 w8 = w[8], w9 = w[9];
        a0 = ffma2(v2[0], w8.x, a0);
        a1 = ffma2(v2[1], w8.y, a1);
        a0 = ffma2(v2[2], w9.x, a0);
        a1 = ffma2(v2[3], w9.y, a1);
        float h = sm[SM_B1 + k] + hsum2(fadd2(a0, a1));
        acc = fmaf(fmaxf(h, 0.f), sm[SM_W2 + k], acc);
    }
    out[m] = acc;
}

// ---------------- launch ----------------
extern "C" void kernel_launch(void* const* d_in, const int* in_sizes, int n_in,
                              void* d_out, int out_size)
{
    const float* coords = (const float*)d_in[0];
    const float* lx  = (const float*)d_in[1];
    const float* ly  = (const float*)d_in[2];
    const float* lz  = (const float*)d_in[3];
    const float* pxy = (const float*)d_in[4];
    const float* pyz = (const float*)d_in[5];
    const float* pxz = (const float*)d_in[6];
    const float* vol = (const float*)d_in[7];
    const float* Wx  = (const float*)d_in[8];
    const float* bx  = (const float*)d_in[9];
    const float* Wy  = (const float*)d_in[10];
    const float* by  = (const float*)d_in[11];
    const float* Wz  = (const float*)d_in[12];
    const float* bz  = (const float*)d_in[13];
    const float* W1  = (const float*)d_in[14];
    const float* b1  = (const float*)d_in[15];
    const float* W2  = (const float*)d_in[16];
    const float* b2  = (const float*)d_in[17];
    float* out = (float*)d_out;

    int M = in_sizes[0] / 3;

    cudaFuncSetAttribute(k_main, cudaFuncAttributeMaxDynamicSharedMemorySize, SMEM_BYTES);

    dim3 tp_grid(16384/32, 3);
    dim3 tp_blk(32, 8);
    k_tplane<<<tp_grid, tp_blk>>>(pxy, pyz, pxz);
    k_tvol<<<262144/128, 256>>>(vol);

    k_main<<<(M + 255) / 256, 256, SMEM_BYTES>>>(coords, lx, ly, lz,
                                                 Wx, bx, Wy, by, Wz, bz,
                                                 W1, b1, W2, b2, out, M);
}

// round 3
// speedup vs baseline: 1.0159x; 1.0009x over previous
#include <cuda_runtime.h>
#include <cuda_fp16.h>
#include <cstdint>

// ---------------- problem constants ----------------
#define PSZ (128*128*32)          // one plane, elements
#define VSZ (64*64*64*8)          // volume, elements

// smem layout (floats)
#define SM_LINES   0          // 3 axes * 128 rows * 36 floats (row = 32ch + 4 pad)
#define SM_WT      13824      // 3*1024 (Wx^T, Wy^T, Wz^T), [j*32+c]
#define SM_W1T     16896      // 128*40, [k*40+j]
#define SM_B       22016      // bx(32) by(32) bz(32)
#define SM_B1      22112      // 128
#define SM_W2      22240      // 128
#define SM_FLOATS  22368
#define SMEM_BYTES (SM_FLOATS*4)

#define LROW 36               // line row stride in floats

// device scratch: channel-last fp16 grids
__device__ __align__(128) __half g_plane_h[3*PSZ];  // [p][(row*128+col)*32 + c]
__device__ __align__(128) __half g_vol_h[VSZ];      // [((z*64+y)*64+x)*8 + c]

typedef unsigned long long ull;

__device__ __forceinline__ ull pk2(float a, float b){ ull r; asm("mov.b64 %0,{%1,%2};":"=l"(r):"f"(a),"f"(b)); return r; }
__device__ __forceinline__ void upk2(ull v, float& a, float& b){ asm("mov.b64 {%0,%1}, %2;":"=f"(a),"=f"(b):"l"(v)); }
__device__ __forceinline__ ull ffma2(ull a, ull b, ull c){ ull d; asm("fma.rn.f32x2 %0,%1,%2,%3;":"=l"(d):"l"(a),"l"(b),"l"(c)); return d; }
__device__ __forceinline__ ull fadd2(ull a, ull b){ ull d; asm("add.rn.f32x2 %0,%1,%2;":"=l"(d):"l"(a),"l"(b)); return d; }
__device__ __forceinline__ float hsum2(ull v){ float a,b; upk2(v,a,b); return a+b; }

// ---------------- preprocessing: transpose to channel-last fp16 ----------------
// planes: src (32, 16384) -> dst (16384, 32) fp16.  32x32 smem tile.
__global__ void k_tplane(const float* __restrict__ pxy, const float* __restrict__ pyz,
                         const float* __restrict__ pxz)
{
    __shared__ float tile[32][33];
    int p   = blockIdx.y;                    // which plane
    int hw0 = blockIdx.x * 32;
    const float* src = (p == 0) ? pxy : (p == 1) ? pyz : pxz;
    __half* dst = g_plane_h + p * PSZ;

    int tx = threadIdx.x;         // 0..31
    int ty = threadIdx.y;         // 0..7
    // read: coalesced in hw
    #pragma unroll
    for (int cc = ty; cc < 32; cc += 8)
        tile[cc][tx] = src[cc * 16384 + hw0 + tx];
    __syncthreads();
    // write: coalesced in (hw*32 + c)
    #pragma unroll
    for (int hwL = ty; hwL < 32; hwL += 8)
        dst[(hw0 + hwL) * 32 + tx] = __float2half(tile[tx][hwL]);
}

// volume: src (8, 262144) -> dst (262144, 8) fp16
__global__ void k_tvol(const float* __restrict__ vol)
{
    __shared__ float t[8][129];
    int vox0 = blockIdx.x * 128;
    int tid  = threadIdx.x;       // 0..255
    int w    = tid >> 5;          // warp = channel
    int lane = tid & 31;
    #pragma unroll
    for (int j = lane; j < 128; j += 32)
        t[w][j] = vol[w * 262144 + vox0 + j];
    __syncthreads();
    #pragma unroll
    for (int rep = 0; rep < 4; rep++) {
        int idx = rep * 256 + tid;            // 0..1023
        int v   = idx >> 3, c = idx & 7;
        g_vol_h[vox0 * 8 + idx] = __float2half(t[c][v]);
    }
}

// ---------------- per-point sampling helpers ----------------
// line: smem channel-last rows, fp32.  eL[q] = relu(lerp) packed f32x2
__device__ __forceinline__ void line_sample(const float* __restrict__ row0, float w, ull* eL)
{
    const float4* A4 = (const float4*)row0;
    const float4* B4 = (const float4*)(row0 + LROW);
#pragma unroll
    for (int q = 0; q < 8; q++) {
        float4 a = A4[q], b = B4[q];
        float e0 = fmaxf(fmaf(w, b.x - a.x, a.x), 0.f);
        float e1 = fmaxf(fmaf(w, b.y - a.y, a.y), 0.f);
        float e2 = fmaxf(fmaf(w, b.z - a.z, a.z), 0.f);
        float e3 = fmaxf(fmaf(w, b.w - a.w, a.w), 0.f);
        eL[2*q]   = pk2(e0, e1);
        eL[2*q+1] = pk2(e2, e3);
    }
}

// plane: channel-last fp16 global, bilinear in half2, relu'd, packed f32x2
__device__ __forceinline__ void plane_sample(const __half* __restrict__ pl, int col, int row,
                                             float wc, float wr, ull* eP)
{
    const uint4* t00 = (const uint4*)(pl + (row*128 + col)*32);
    const uint4* t01 = t00 + 4;      // col+1: +32 halves = 4 uint4
    const uint4* t10 = t00 + 512;    // row+1: +4096 halves
    const uint4* t11 = t10 + 4;
    float iwc = 1.f - wc, iwr = 1.f - wr;
    __half2 w00 = __float2half2_rn(iwc*iwr);
    __half2 w01 = __float2half2_rn( wc*iwr);
    __half2 w10 = __float2half2_rn(iwc* wr);
    __half2 w11 = __float2half2_rn( wc* wr);
#pragma unroll
    for (int h = 0; h < 4; h++) {
        uint4 A = t00[h], B = t01[h], C = t10[h], D = t11[h];
        const __half2* a = (const __half2*)&A;
        const __half2* b = (const __half2*)&B;
        const __half2* c = (const __half2*)&C;
        const __half2* d = (const __half2*)&D;
#pragma unroll
        for (int k = 0; k < 4; k++) {
            __half2 acc = __hmul2(w00, a[k]);
            __half2 ac2 = __hmul2(w01, b[k]);
            acc = __hfma2(w10, c[k], acc);
            ac2 = __hfma2(w11, d[k], ac2);
            acc = __hadd2(acc, ac2);
            float2 f = __half22float2(acc);
            eP[h*4 + k] = pk2(fmaxf(f.x, 0.f), fmaxf(f.y, 0.f));
        }
    }
}

// feat[j] (+)= (b[j] + eL.Wt_j) * (b[j] + eP.Wt_j)
template<bool ADD>
__device__ __forceinline__ void axis_combine(const ull* eL, const ull* eP,
                                             const float* __restrict__ Wt,
                                             const float* __restrict__ bias,
                                             float* feat)
{
#pragma unroll 4
    for (int j = 0; j < 32; j++) {
        const ulonglong2* w = (const ulonglong2*)(Wt + (j << 5));
        ull a0 = 0ull, a1 = 0ull, p0 = 0ull, p1 = 0ull;
#pragma unroll
        for (int q = 0; q < 8; q++) {
            ulonglong2 ww = w[q];
            a0 = ffma2(eL[2*q],   ww.x, a0);
            a1 = ffma2(eL[2*q+1], ww.y, a1);
            p0 = ffma2(eP[2*q],   ww.x, p0);
            p1 = ffma2(eP[2*q+1], ww.y, p1);
        }
        float b  = bias[j];
        float t1 = b + hsum2(fadd2(a0, a1));
        float t2 = b + hsum2(fadd2(p0, p1));
        if (ADD) feat[j] += t1 * t2; else feat[j] = t1 * t2;
    }
}

// ---------------- main fused kernel ----------------
__global__ void __launch_bounds__(256, 2) k_main(
    const float* __restrict__ coords,
    const float* __restrict__ lx, const float* __restrict__ ly, const float* __restrict__ lz,
    const float* __restrict__ Wx, const float* __restrict__ bx,
    const float* __restrict__ Wy, const float* __restrict__ by,
    const float* __restrict__ Wz, const float* __restrict__ bz,
    const float* __restrict__ W1, const float* __restrict__ b1,
    const float* __restrict__ W2, const float* __restrict__ b2,
    float* __restrict__ out, int M)
{
    extern __shared__ float sm[];

    // lines: channel-last rows, stride LROW
    for (int i = threadIdx.x; i < 4096; i += 256) {
        int pos = i >> 5, c = i & 31;
        sm[SM_LINES             + pos*LROW + c] = lx[c*128 + pos];
        sm[SM_LINES + 128*LROW  + pos*LROW + c] = ly[c*128 + pos];
        sm[SM_LINES + 256*LROW  + pos*LROW + c] = lz[c*128 + pos];
    }
    for (int i = threadIdx.x; i < 1024; i += 256) {
        int j = i & 31, c = i >> 5;                 // input W[c*32+j]
        sm[SM_WT        + j*32 + c] = Wx[i];
        sm[SM_WT + 1024 + j*32 + c] = Wy[i];
        sm[SM_WT + 2048 + j*32 + c] = Wz[i];
    }
    for (int i = threadIdx.x; i < 5120; i += 256) {
        int j = i >> 7, k = i & 127;                // input W1[j*128+k]
        sm[SM_W1T + k*40 + j] = W1[i];
    }
    if (threadIdx.x < 32) {
        sm[SM_B      + threadIdx.x] = bx[threadIdx.x];
        sm[SM_B + 32 + threadIdx.x] = by[threadIdx.x];
        sm[SM_B + 64 + threadIdx.x] = bz[threadIdx.x];
    }
    for (int i = threadIdx.x; i < 128; i += 256) {
        sm[SM_B1 + i] = b1[i];
        sm[SM_W2 + i] = W2[i];
    }
    __syncthreads();

    int m = blockIdx.x * blockDim.x + threadIdx.x;
    if (m >= M) return;

    float x = coords[3*m + 0];
    float y = coords[3*m + 1];
    float z = coords[3*m + 2];

    // 128-grid indices (lines & planes)
    float fx = (x + 1.f) * (0.5f * 127.f);
    float fy = (y + 1.f) * (0.5f * 127.f);
    float fz = (z + 1.f) * (0.5f * 127.f);
    float fix = fminf(fmaxf(floorf(fx), 0.f), 126.f);
    float fiy = fminf(fmaxf(floorf(fy), 0.f), 126.f);
    float fiz = fminf(fmaxf(floorf(fz), 0.f), 126.f);
    int ix = (int)fix, iy = (int)fiy, iz = (int)fiz;
    float wxp = fx - fix, wyp = fy - fiy, wzp = fz - fiz;

    // 64-grid (volume)
    float gx = (x + 1.f) * (0.5f * 63.f);
    float gy = (y + 1.f) * (0.5f * 63.f);
    float gz = (z + 1.f) * (0.5f * 63.f);
    float gvx = fminf(fmaxf(floorf(gx), 0.f), 62.f);
    float gvy = fminf(fmaxf(floorf(gy), 0.f), 62.f);
    float gvz = fminf(fmaxf(floorf(gz), 0.f), 62.f);
    int vx = (int)gvx, vy = (int)gvy, vz = (int)gvz;
    float ux = gx - gvx, uy = gy - gvy, uz = gz - gvz;

    float feat[32];
    ull eL[16], eP[16];

    // ---- axis X: xtran(line_x, Wx) * yztran(plane_yz, Wx)
    line_sample(sm + SM_LINES + ix*LROW, wxp, eL);
    plane_sample(g_plane_h + PSZ, iy, iz, wyp, wzp, eP);       // plane_yz: col=y, row=z
    axis_combine<false>(eL, eP, sm + SM_WT,        sm + SM_B,      feat);

    // ---- axis Y: ytran(line_y, Wy) * xztran(plane_xz, Wy)
    line_sample(sm + SM_LINES + 128*LROW + iy*LROW, wyp, eL);
    plane_sample(g_plane_h + 2*PSZ, ix, iz, wxp, wzp, eP);     // plane_xz: col=x, row=z
    axis_combine<true>(eL, eP, sm + SM_WT + 1024,  sm + SM_B + 32, feat);

    // ---- axis Z: ztran(line_z, Wz) * xytran(plane_xy, Wz)
    line_sample(sm + SM_LINES + 256*LROW + iz*LROW, wzp, eL);
    plane_sample(g_plane_h, ix, iy, wxp, wyp, eP);             // plane_xy: col=x, row=y
    axis_combine<true>(eL, eP, sm + SM_WT + 2048,  sm + SM_B + 64, feat);

    // ---- volume trilinear (raw, no relu) in half2, -> v2[4] f32x2 (8 channels)
    ull v2[4];
    {
        const uint4* vb = (const uint4*)(g_vol_h + ((((vz*64 + vy)*64) + vx) << 3));
        float iux = 1.f - ux, iuy = 1.f - uy, iuz = 1.f - uz;
        __half2 va[4] = {__half2(), __half2(), __half2(), __half2()};
        va[0] = __float2half2_rn(0.f); va[1] = va[0]; va[2] = va[0]; va[3] = va[0];
#pragma unroll
        for (int corner = 0; corner < 8; corner++) {
            int dx = corner & 1, dy = (corner >> 1) & 1, dz = corner >> 2;
            float wgt = (dx ? ux : iux) * (dy ? uy : iuy) * (dz ? uz : iuz);
            __half2 w2 = __float2half2_rn(wgt);
            uint4 T = vb[dx + dy*64 + dz*4096];
            const __half2* t = (const __half2*)&T;
            va[0] = __hfma2(w2, t[0], va[0]);
            va[1] = __hfma2(w2, t[1], va[1]);
            va[2] = __hfma2(w2, t[2], va[2]);
            va[3] = __hfma2(w2, t[3], va[3]);
        }
#pragma unroll
        for (int q = 0; q < 4; q++) {
            float2 f = __half22float2(va[q]);
            v2[q] = pk2(f.x, f.y);
        }
    }

    // ---- final MLP: h = relu([feat, xyz_e] @ W1 + b1); out = h @ W2 + b2
    ull f2[16];
#pragma unroll
    for (int q = 0; q < 16; q++) f2[q] = pk2(feat[2*q], feat[2*q+1]);

    float acc = b2[0];
#pragma unroll 2
    for (int k = 0; k < 128; k++) {
        const ulonglong2* w = (const ulonglong2*)(sm + SM_W1T + k*40);
        ull a0 = 0ull, a1 = 0ull;
#pragma unroll
        for (int q = 0; q < 8; q++) {
            ulonglong2 ww = w[q];
            a0 = ffma2(f2[2*q],   ww.x, a0);
            a1 = ffma2(f2[2*q+1], ww.y, a1);
        }
        ulonglong2 w8 = w[8], w9 = w[9];
        a0 = ffma2(v2[0], w8.x, a0);
        a1 = ffma2(v2[1], w8.y, a1);
        a0 = ffma2(v2[2], w9.x, a0);
        a1 = ffma2(v2[3], w9.y, a1);
        float h = sm[SM_B1 + k] + hsum2(fadd2(a0, a1));
        acc = fmaf(fmaxf(h, 0.f), sm[SM_W2 + k], acc);
    }
    out[m] = acc;
}

// ---------------- launch ----------------
extern "C" void kernel_launch(void* const* d_in, const int* in_sizes, int n_in,
                              void* d_out, int out_size)
{
    const float* coords = (const float*)d_in[0];
    const float* lx  = (const float*)d_in[1];
    const float* ly  = (const float*)d_in[2];
    const float* lz  = (const float*)d_in[3];
    const float* pxy = (const float*)d_in[4];
    const float* pyz = (const float*)d_in[5];
    const float* pxz = (const float*)d_in[6];
    const float* vol = (const float*)d_in[7];
    const float* Wx  = (const float*)d_in[8];
    const float* bx  = (const float*)d_in[9];
    const float* Wy  = (const float*)d_in[10];
    const float* by  = (const float*)d_in[11];
    const float* Wz  = (const float*)d_in[12];
    const float* bz  = (const float*)d_in[13];
    const float* W1  = (const float*)d_in[14];
    const float* b1  = (const float*)d_in[15];
    const float* W2  = (const float*)d_in[16];
    const float* b2  = (const float*)d_in[17];
    float* out = (float*)d_out;

    int M = in_sizes[0] / 3;

    cudaFuncSetAttribute(k_main, cudaFuncAttributeMaxDynamicSharedMemorySize, SMEM_BYTES);

    dim3 tp_grid(16384/32, 3);
    dim3 tp_blk(32, 8);
    k_tplane<<<tp_grid, tp_blk>>>(pxy, pyz, pxz);
    k_tvol<<<262144/128, 256>>>(vol);

    k_main<<<(M + 255) / 256, 256, SMEM_BYTES>>>(coords, lx, ly, lz,
                                                 Wx, bx, Wy, by, Wz, bz,
                                                 W1, b1, W2, b2, out, M);
}

// round 4
// speedup vs baseline: 1.9757x; 1.9448x over previous
#include <cuda_runtime.h>
#include <cuda_fp16.h>
#include <cstdint>

#define PSZ (128*128*32)
#define VSZ (64*64*64*8)

// device scratch: channel-last fp16 grids
__device__ __align__(128) __half g_plane_h[3*PSZ];   // [p][(row*128+col)*32 + c]
__device__ __align__(128) __half g_vol_h[VSZ];       // [((z*64+y)*64+x)*8 + c]

// ---------------- smem byte layout ----------------
#define ESTG_OFF  0                    // 8 warps * 5120 (L:2560, P:2560); row stride 80B
#define LINES_OFF 40960                // 3 * 128 * 80 (40 halves/row, 32 used)
#define WBF_OFF   71680                // 3ax*4nt*2kt*32lane*2 uints = 6144B
#define WB1F_OFF  77824                // 16nt*3kt*32lane*2 uints = 12288B
#define VST_OFF   90112                // 8 warps * 32 lanes * 16B = 4096B
#define BAX_OFF   94208                // 3*32 f32
#define B1S_OFF   94592                // 128 f32
#define W2S_OFF   95104                // 128 f32
#define SMEM_BYTES 95616

// ---------------- preprocessing ----------------
__global__ void k_tplane(const float* __restrict__ pxy, const float* __restrict__ pyz,
                         const float* __restrict__ pxz)
{
    __shared__ float tile[32][33];
    int p   = blockIdx.y;
    int hw0 = blockIdx.x * 32;
    const float* src = (p == 0) ? pxy : (p == 1) ? pyz : pxz;
    __half* dst = g_plane_h + p * PSZ;
    int tx = threadIdx.x, ty = threadIdx.y;
    #pragma unroll
    for (int cc = ty; cc < 32; cc += 8)
        tile[cc][tx] = src[cc * 16384 + hw0 + tx];
    __syncthreads();
    #pragma unroll
    for (int hwL = ty; hwL < 32; hwL += 8)
        dst[(hw0 + hwL) * 32 + tx] = __float2half(tile[tx][hwL]);
}

__global__ void k_tvol(const float* __restrict__ vol)
{
    __shared__ float t[8][129];
    int vox0 = blockIdx.x * 128;
    int tid  = threadIdx.x;
    int w = tid >> 5, lane = tid & 31;
    #pragma unroll
    for (int j = lane; j < 128; j += 32)
        t[w][j] = vol[w * 262144 + vox0 + j];
    __syncthreads();
    #pragma unroll
    for (int rep = 0; rep < 4; rep++) {
        int idx = rep * 256 + tid;
        int v = idx >> 3, c = idx & 7;
        g_vol_h[vox0 * 8 + idx] = __float2half(t[c][v]);
    }
}

// ---------------- warp MMA helpers ----------------
__device__ __forceinline__ void mma16816(float c[4], const unsigned a[4], const unsigned b[2])
{
    asm volatile("mma.sync.aligned.m16n8k16.row.col.f32.f16.f16.f32 "
        "{%0,%1,%2,%3}, {%4,%5,%6,%7}, {%8,%9}, {%0,%1,%2,%3};\n"
        : "+f"(c[0]), "+f"(c[1]), "+f"(c[2]), "+f"(c[3])
        : "r"(a[0]), "r"(a[1]), "r"(a[2]), "r"(a[3]), "r"(b[0]), "r"(b[1]));
}
__device__ __forceinline__ void ldsm4(unsigned r[4], unsigned addr)
{
    asm volatile("ldmatrix.sync.aligned.m8n8.x4.shared.b16 {%0,%1,%2,%3}, [%4];"
        : "=r"(r[0]), "=r"(r[1]), "=r"(r[2]), "=r"(r[3]) : "r"(addr));
}
__device__ __forceinline__ unsigned packh2(float a, float b)
{
    __half2 h = __floats2half2_rn(a, b);
    return *(unsigned*)&h;
}

// ---------------- main fused kernel ----------------
__global__ void __launch_bounds__(256, 2) k_main(
    const float* __restrict__ coords,
    const float* __restrict__ lx, const float* __restrict__ ly, const float* __restrict__ lz,
    const float* __restrict__ Wx, const float* __restrict__ bx,
    const float* __restrict__ Wy, const float* __restrict__ by,
    const float* __restrict__ Wz, const float* __restrict__ bz,
    const float* __restrict__ W1, const float* __restrict__ b1,
    const float* __restrict__ W2, const float* __restrict__ b2,
    float* __restrict__ out, int M)
{
    extern __shared__ char smem[];
    int tid = threadIdx.x;

    // ---- init: lines fp16 channel-last ----
    {
        __half* Lh = (__half*)(smem + LINES_OFF);
        for (int i = tid; i < 3*4096; i += 256) {
            int ax = i >> 12, r = i & 4095, pos = r >> 5, c = r & 31;
            const float* s = (ax == 0) ? lx : (ax == 1) ? ly : lz;
            Lh[ax*5120 + pos*40 + c] = __float2half(s[c*128 + pos]);
        }
    }
    // ---- init: axis-weight B fragments ----
    {
        unsigned* wb = (unsigned*)(smem + WBF_OFF);
        for (int i = tid; i < 1536; i += 256) {
            int ax = i >> 8, r = i & 255;
            int nt = r >> 6, r2 = r & 63, kt = r2 >> 5, ln = r2 & 31;
            int gg = ln >> 2, tt = ln & 3;
            int n = nt*8 + gg, k0 = kt*16 + 2*tt;
            const float* W = (ax == 0) ? Wx : (ax == 1) ? Wy : Wz;
            wb[i*2 + 0] = packh2(W[k0*32 + n],     W[(k0+1)*32 + n]);
            wb[i*2 + 1] = packh2(W[(k0+8)*32 + n], W[(k0+9)*32 + n]);
        }
    }
    // ---- init: W1 B fragments (K padded 40->48 with zeros) ----
    {
        unsigned* wb = (unsigned*)(smem + WB1F_OFF);
        for (int i = tid; i < 1536; i += 256) {
            int nt = i / 96, r = i - nt*96, kt = r >> 5, ln = r & 31;
            int gg = ln >> 2, tt = ln & 3;
            int n = nt*8 + gg, k0 = kt*16 + 2*tt;
            float v0 = (k0   < 40) ? W1[(k0  )*128 + n] : 0.f;
            float v1 = (k0+1 < 40) ? W1[(k0+1)*128 + n] : 0.f;
            float v2 = (k0+8 < 40) ? W1[(k0+8)*128 + n] : 0.f;
            float v3 = (k0+9 < 40) ? W1[(k0+9)*128 + n] : 0.f;
            wb[i*2 + 0] = packh2(v0, v1);
            wb[i*2 + 1] = packh2(v2, v3);
        }
    }
    {
        float* ba = (float*)(smem + BAX_OFF);
        for (int i = tid; i < 96; i += 256)
            ba[i] = (i < 32) ? bx[i] : (i < 64) ? by[i-32] : bz[i-64];
        float* s1 = (float*)(smem + B1S_OFF);
        float* s2 = (float*)(smem + W2S_OFF);
        for (int i = tid; i < 128; i += 256) { s1[i] = b1[i]; s2[i] = W2[i]; }
    }
    __syncthreads();

    int lane = tid & 31, warp = tid >> 5;
    int g = lane >> 2, t = lane & 3;
    int tile0 = blockIdx.x * 256 + warp * 32;
    int m  = tile0 + lane;
    int mc = min(m, M - 1);

    float x = coords[3*mc + 0];
    float y = coords[3*mc + 1];
    float z = coords[3*mc + 2];

    float fx = (x + 1.f) * (0.5f * 127.f);
    float fy = (y + 1.f) * (0.5f * 127.f);
    float fz = (z + 1.f) * (0.5f * 127.f);
    float fix = fminf(fmaxf(floorf(fx), 0.f), 126.f);
    float fiy = fminf(fmaxf(floorf(fy), 0.f), 126.f);
    float fiz = fminf(fmaxf(floorf(fz), 0.f), 126.f);
    int ix = (int)fix, iy = (int)fiy, iz = (int)fiz;
    float wxp = fx - fix, wyp = fy - fiy, wzp = fz - fiz;

    float gx = (x + 1.f) * (0.5f * 63.f);
    float gy = (y + 1.f) * (0.5f * 63.f);
    float gz = (z + 1.f) * (0.5f * 63.f);
    float gvx = fminf(fmaxf(floorf(gx), 0.f), 62.f);
    float gvy = fminf(fmaxf(floorf(gy), 0.f), 62.f);
    float gvz = fminf(fmaxf(floorf(gz), 0.f), 62.f);
    int vx = (int)gvx, vy = (int)gvy, vz = (int)gvz;
    float ux = gx - gvx, uy = gy - gvy, uz = gz - gvz;

    // ---- volume trilinear -> VST (16B per lane) ----
    {
        const uint4* vb = (const uint4*)(g_vol_h + ((((vz*64 + vy)*64) + vx) << 3));
        float iux = 1.f - ux, iuy = 1.f - uy, iuz = 1.f - uz;
        __half2 z2 = __float2half2_rn(0.f);
        __half2 va0 = z2, va1 = z2, va2 = z2, va3 = z2;
#pragma unroll
        for (int corner = 0; corner < 8; corner++) {
            int dx = corner & 1, dy = (corner >> 1) & 1, dz = corner >> 2;
            float wgt = (dx ? ux : iux) * (dy ? uy : iuy) * (dz ? uz : iuz);
            __half2 w2 = __float2half2_rn(wgt);
            uint4 T = vb[dx + dy*64 + dz*4096];
            const __half2* th = (const __half2*)&T;
            va0 = __hfma2(w2, th[0], va0);
            va1 = __hfma2(w2, th[1], va1);
            va2 = __hfma2(w2, th[2], va2);
            va3 = __hfma2(w2, th[3], va3);
        }
        uint4* vr = (uint4*)(smem + VST_OFF + warp*512 + lane*16);
        uint4 o;
        o.x = *(unsigned*)&va0; o.y = *(unsigned*)&va1;
        o.z = *(unsigned*)&va2; o.w = *(unsigned*)&va3;
        *vr = o;
    }

    // per-axis parameters
    int ixs[3] = { ix, iy, iz };
    float wls[3] = { wxp, wyp, wzp };
    const __half* plb[3] = { g_plane_h + PSZ, g_plane_h + 2*PSZ, g_plane_h };
    int pcol[3] = { iy, ix, ix };
    int prow[3] = { iz, iz, iy };
    float pwc[3] = { wyp, wxp, wxp };
    float pwr[3] = { wzp, wzp, wyp };

    char* eL_base = smem + ESTG_OFF + warp*5120;
    char* eP_base = eL_base + 2560;
    unsigned sbase = (unsigned)__cvta_generic_to_shared(smem);
    unsigned eL_u = sbase + ESTG_OFF + warp*5120;
    unsigned eP_u = eL_u + 2560;
    int rowpart = (lane & 15)*80 + ((lane >> 4) << 4);

    const __half2 z2 = __float2half2_rn(0.f);
    float feat[2][4][4];

#pragma unroll
    for (int ax = 0; ax < 3; ax++) {
        // line sample -> eL staging (32 halves, relu'd)
        {
            const uint4* A4 = (const uint4*)(smem + LINES_OFF + ax*10240 + ixs[ax]*80);
            const uint4* B4 = (const uint4*)((const char*)A4 + 80);
            __half2 wv = __float2half2_rn(wls[ax]);
            __half2 iwv = __float2half2_rn(1.f - wls[ax]);
            uint4* dst = (uint4*)(eL_base + lane*80);
#pragma unroll
            for (int q = 0; q < 4; q++) {
                uint4 a = A4[q], b = B4[q];
                const __half2* ah = (const __half2*)&a;
                const __half2* bh = (const __half2*)&b;
                uint4 o;
                unsigned* oh = (unsigned*)&o;
#pragma unroll
                for (int j = 0; j < 4; j++) {
                    __half2 e = __hfma2(wv, bh[j], __hmul2(iwv, ah[j]));
                    e = __hmax2(e, z2);
                    oh[j] = *(unsigned*)&e;
                }
                dst[q] = o;
            }
        }
        // plane sample -> eP staging (bilinear, relu'd)
        {
            const uint4* t00 = (const uint4*)(plb[ax] + (size_t)(prow[ax]*128 + pcol[ax])*32);
            const uint4* t01 = t00 + 4;
            const uint4* t10 = t00 + 512;
            const uint4* t11 = t10 + 4;
            float wc = pwc[ax], wr = pwr[ax];
            float iwc = 1.f - wc, iwr = 1.f - wr;
            __half2 w00 = __float2half2_rn(iwc*iwr);
            __half2 w01 = __float2half2_rn( wc*iwr);
            __half2 w10 = __float2half2_rn(iwc* wr);
            __half2 w11 = __float2half2_rn( wc* wr);
            uint4* dst = (uint4*)(eP_base + lane*80);
#pragma unroll
            for (int h = 0; h < 4; h++) {
                uint4 A = t00[h], B = t01[h], C = t10[h], D = t11[h];
                const __half2* a = (const __half2*)&A;
                const __half2* b = (const __half2*)&B;
                const __half2* c = (const __half2*)&C;
                const __half2* d = (const __half2*)&D;
                uint4 o;
                unsigned* oh = (unsigned*)&o;
#pragma unroll
                for (int k = 0; k < 4; k++) {
                    __half2 acc = __hmul2(w00, a[k]);
                    __half2 ac2 = __hmul2(w01, b[k]);
                    acc = __hfma2(w10, c[k], acc);
                    ac2 = __hfma2(w11, d[k], ac2);
                    acc = __hadd2(acc, ac2);
                    acc = __hmax2(acc, z2);
                    oh[k] = *(unsigned*)&acc;
                }
                dst[h] = o;
            }
        }
        __syncwarp();

        unsigned aL[2][2][4], aP[2][2][4];
#pragma unroll
        for (int mt = 0; mt < 2; mt++)
#pragma unroll
        for (int kt = 0; kt < 2; kt++) {
            ldsm4(aL[mt][kt], eL_u + mt*16*80 + kt*32 + rowpart);
            ldsm4(aP[mt][kt], eP_u + mt*16*80 + kt*32 + rowpart);
        }
        __syncwarp();

        const unsigned* wb = (const unsigned*)(smem + WBF_OFF) + ax*512;
        const float* ba = (const float*)(smem + BAX_OFF) + ax*32;
#pragma unroll
        for (int nt = 0; nt < 4; nt++) {
            unsigned bf[2][2];
            bf[0][0] = wb[((nt*2+0)*32 + lane)*2 + 0];
            bf[0][1] = wb[((nt*2+0)*32 + lane)*2 + 1];
            bf[1][0] = wb[((nt*2+1)*32 + lane)*2 + 0];
            bf[1][1] = wb[((nt*2+1)*32 + lane)*2 + 1];
            float2 bb = *(const float2*)(ba + nt*8 + 2*t);
#pragma unroll
            for (int mt = 0; mt < 2; mt++) {
                float tl[4] = {0.f,0.f,0.f,0.f};
                float tp[4] = {0.f,0.f,0.f,0.f};
                mma16816(tl, aL[mt][0], bf[0]);
                mma16816(tl, aL[mt][1], bf[1]);
                mma16816(tp, aP[mt][0], bf[0]);
                mma16816(tp, aP[mt][1], bf[1]);
                float v0 = (tl[0] + bb.x) * (tp[0] + bb.x);
                float v1 = (tl[1] + bb.y) * (tp[1] + bb.y);
                float v2 = (tl[2] + bb.x) * (tp[2] + bb.x);
                float v3 = (tl[3] + bb.y) * (tp[3] + bb.y);
                if (ax == 0) {
                    feat[mt][nt][0] = v0; feat[mt][nt][1] = v1;
                    feat[mt][nt][2] = v2; feat[mt][nt][3] = v3;
                } else {
                    feat[mt][nt][0] += v0; feat[mt][nt][1] += v1;
                    feat[mt][nt][2] += v2; feat[mt][nt][3] += v3;
                }
            }
        }
    }

    // ---- MLP A fragments: feat (K 0..31) + vol (K 32..39) + zeros (40..47) ----
    __syncwarp();
    unsigned aM[2][3][4];
    const unsigned* vst = (const unsigned*)(smem + VST_OFF + warp*512);
#pragma unroll
    for (int mt = 0; mt < 2; mt++) {
#pragma unroll
        for (int kt = 0; kt < 2; kt++) {
            aM[mt][kt][0] = packh2(feat[mt][2*kt][0],   feat[mt][2*kt][1]);
            aM[mt][kt][1] = packh2(feat[mt][2*kt][2],   feat[mt][2*kt][3]);
            aM[mt][kt][2] = packh2(feat[mt][2*kt+1][0], feat[mt][2*kt+1][1]);
            aM[mt][kt][3] = packh2(feat[mt][2*kt+1][2], feat[mt][2*kt+1][3]);
        }
        aM[mt][2][0] = vst[(mt*16 + g)*4 + t];
        aM[mt][2][1] = vst[(mt*16 + g + 8)*4 + t];
        aM[mt][2][2] = 0u;
        aM[mt][2][3] = 0u;
    }

    // ---- MLP MMAs + fused relu + W2 dot ----
    float s0[2] = {0.f, 0.f}, s1[2] = {0.f, 0.f};
    const unsigned* wb1 = (const unsigned*)(smem + WB1F_OFF);
    const float* b1s = (const float*)(smem + B1S_OFF);
    const float* w2s = (const float*)(smem + W2S_OFF);
#pragma unroll
    for (int nt = 0; nt < 16; nt++) {
        unsigned bf[3][2];
#pragma unroll
        for (int kt = 0; kt < 3; kt++) {
            bf[kt][0] = wb1[((nt*3 + kt)*32 + lane)*2 + 0];
            bf[kt][1] = wb1[((nt*3 + kt)*32 + lane)*2 + 1];
        }
        float2 bb = *(const float2*)(b1s + nt*8 + 2*t);
        float2 w2 = *(const float2*)(w2s + nt*8 + 2*t);
#pragma unroll
        for (int mt = 0; mt < 2; mt++) {
            float c[4] = {0.f,0.f,0.f,0.f};
            mma16816(c, aM[mt][0], bf[0]);
            mma16816(c, aM[mt][1], bf[1]);
            mma16816(c, aM[mt][2], bf[2]);
            s0[mt] += fmaxf(c[0] + bb.x, 0.f)*w2.x + fmaxf(c[1] + bb.y, 0.f)*w2.y;
            s1[mt] += fmaxf(c[2] + bb.x, 0.f)*w2.x + fmaxf(c[3] + bb.y, 0.f)*w2.y;
        }
    }

    // ---- quad reduce + store ----
    float bias2 = b2[0];
#pragma unroll
    for (int mt = 0; mt < 2; mt++) {
        s0[mt] += __shfl_xor_sync(0xffffffffu, s0[mt], 1);
        s0[mt] += __shfl_xor_sync(0xffffffffu, s0[mt], 2);
        s1[mt] += __shfl_xor_sync(0xffffffffu, s1[mt], 1);
        s1[mt] += __shfl_xor_sync(0xffffffffu, s1[mt], 2);
    }
    if (t == 0) {
#pragma unroll
        for (int mt = 0; mt < 2; mt++) {
            int p0 = tile0 + mt*16 + g;
            int p1 = p0 + 8;
            if (p0 < M) out[p0] = s0[mt] + bias2;
            if (p1 < M) out[p1] = s1[mt] + bias2;
        }
    }
}

// ---------------- launch ----------------
extern "C" void kernel_launch(void* const* d_in, const int* in_sizes, int n_in,
                              void* d_out, int out_size)
{
    const float* coords = (const float*)d_in[0];
    const float* lx  = (const float*)d_in[1];
    const float* ly  = (const float*)d_in[2];
    const float* lz  = (const float*)d_in[3];
    const float* pxy = (const float*)d_in[4];
    const float* pyz = (const float*)d_in[5];
    const float* pxz = (const float*)d_in[6];
    const float* vol = (const float*)d_in[7];
    const float* Wx  = (const float*)d_in[8];
    const float* bx  = (const float*)d_in[9];
    const float* Wy  = (const float*)d_in[10];
    const float* by  = (const float*)d_in[11];
    const float* Wz  = (const float*)d_in[12];
    const float* bz  = (const float*)d_in[13];
    const float* W1  = (const float*)d_in[14];
    const float* b1  = (const float*)d_in[15];
    const float* W2  = (const float*)d_in[16];
    const float* b2  = (const float*)d_in[17];
    float* out = (float*)d_out;

    int M = in_sizes[0] / 3;

    cudaFuncSetAttribute(k_main, cudaFuncAttributeMaxDynamicSharedMemorySize, SMEM_BYTES);

    dim3 tp_grid(16384/32, 3);
    dim3 tp_blk(32, 8);
    k_tplane<<<tp_grid, tp_blk>>>(pxy, pyz, pxz);
    k_tvol<<<262144/128, 256>>>(vol);

    k_main<<<(M + 255) / 256, 256, SMEM_BYTES>>>(coords, lx, ly, lz,
                                                 Wx, bx, Wy, by, Wz, bz,
                                                 W1, b1, W2, b2, out, M);
}